// round 11
// baseline (speedup 1.0000x reference)
#include <cuda_runtime.h>
#include <cuda_fp16.h>
#include <math.h>

#define NN 8192
#define DD 256
#define HH 64

// Pre-scaled features: he[j, d] = e_j * h[j, d], fp16 (4 MB, L2-resident).
__device__ __half g_he[NN * DD];

// ---------------------------------------------------------------------------
// Kernel 1 (PDL primary): e = sigmoid(relu(h@W1+b1)@W2+b2); emit he (fp16).
// Triggers programmatic launch completion at entry so the agg kernel's
// A-scan overlaps with this kernel's execution.
// 32 rows/block, 128 threads = 8 rowgroups(x4 rows) x 16 jgroups(x4 j).
// ---------------------------------------------------------------------------
#define MLP_ROWS 32
__global__ void __launch_bounds__(128) mlp_kernel(
    const float* __restrict__ h, const float* __restrict__ W1,
    const float* __restrict__ b1, const float* __restrict__ W2,
    const float* __restrict__ b2, float* __restrict__ out_e) {

#if __CUDA_ARCH__ >= 900
  cudaTriggerProgrammaticLaunchCompletion();   // let agg start its A-scan now
#endif

  __shared__ __align__(16) float sh_h[MLP_ROWS * DD];   // 32 KB
  __shared__ float sPart[MLP_ROWS][17];
  __shared__ float sE[MLP_ROWS];

  const int tid = threadIdx.x;
  const int rg = tid >> 4;                  // 0..7  -> rows rg*4 .. +3
  const int jg = tid & 15;                  // 0..15 -> j jg*4 .. +3
  const int j0 = jg * 4;
  const int rowbase = blockIdx.x * MLP_ROWS;

  {
    const float4* src = (const float4*)(h + (size_t)rowbase * DD);
    float4* dst = (float4*)sh_h;
    #pragma unroll
    for (int i = tid; i < MLP_ROWS * DD / 4; i += 128) dst[i] = __ldg(&src[i]);
  }
  __syncthreads();

  float acc[4][4];
  {
    const float4 b = __ldg((const float4*)(b1 + j0));
    #pragma unroll
    for (int a = 0; a < 4; a++) {
      acc[a][0] = b.x; acc[a][1] = b.y; acc[a][2] = b.z; acc[a][3] = b.w;
    }
  }

  const float4* sh4 = (const float4*)sh_h;
  const float4* W14 = (const float4*)W1;    // row k = 16 float4 over j

  #pragma unroll 4
  for (int k4 = 0; k4 < DD / 4; k4++) {
    float4 hv[4];
    #pragma unroll
    for (int a = 0; a < 4; a++)
      hv[a] = sh4[(rg * 4 + a) * (DD / 4) + k4];        // 16-way broadcast

    const float4 wA = __ldg(&W14[(k4 * 4 + 0) * 16 + jg]);
    const float4 wB = __ldg(&W14[(k4 * 4 + 1) * 16 + jg]);
    const float4 wC = __ldg(&W14[(k4 * 4 + 2) * 16 + jg]);
    const float4 wD = __ldg(&W14[(k4 * 4 + 3) * 16 + jg]);

    #pragma unroll
    for (int a = 0; a < 4; a++) {
      acc[a][0] = fmaf(hv[a].x, wA.x, fmaf(hv[a].y, wB.x, fmaf(hv[a].z, wC.x, fmaf(hv[a].w, wD.x, acc[a][0]))));
      acc[a][1] = fmaf(hv[a].x, wA.y, fmaf(hv[a].y, wB.y, fmaf(hv[a].z, wC.y, fmaf(hv[a].w, wD.y, acc[a][1]))));
      acc[a][2] = fmaf(hv[a].x, wA.z, fmaf(hv[a].y, wB.z, fmaf(hv[a].z, wC.z, fmaf(hv[a].w, wD.z, acc[a][2]))));
      acc[a][3] = fmaf(hv[a].x, wA.w, fmaf(hv[a].y, wB.w, fmaf(hv[a].z, wC.w, fmaf(hv[a].w, wD.w, acc[a][3]))));
    }
  }

  {
    const float4 w2 = __ldg((const float4*)(W2 + j0));
    #pragma unroll
    for (int a = 0; a < 4; a++) {
      sPart[rg * 4 + a][jg] =
          fmaxf(acc[a][0], 0.0f) * w2.x + fmaxf(acc[a][1], 0.0f) * w2.y +
          fmaxf(acc[a][2], 0.0f) * w2.z + fmaxf(acc[a][3], 0.0f) * w2.w;
    }
  }
  __syncthreads();

  if (tid < MLP_ROWS) {
    float s = __ldg(&b2[0]);
    #pragma unroll
    for (int g = 0; g < 16; g++) s += sPart[tid][g];
    const float ev = 1.0f / (1.0f + expf(-s));
    sE[tid] = ev;
    out_e[rowbase + tid] = ev;
  }
  __syncthreads();

  __half2* he2 = (__half2*)g_he;
  #pragma unroll
  for (int i = tid; i < MLP_ROWS * (DD / 4); i += 128) {
    const int r = i >> 6;
    const float4 hv = ((const float4*)sh_h)[i];
    const float e = sE[r];
    const size_t base = ((size_t)rowbase * DD + i * 4) >> 1;
    he2[base]     = __floats2half2_rn(hv.x * e, hv.y * e);
    he2[base + 1] = __floats2half2_rn(hv.z * e, hv.w * e);
  }
}

// ---------------------------------------------------------------------------
// Kernel 2 (PDL secondary; agg core identical to the 50.75us measured best):
// h_out[i,:] = sum_{j: A[i,j] > 0} he[j,:]
// Scan its A row (no dependency on mlp) -> cudaGridDependencySynchronize()
// (waits for mlp grid completion) -> gather.
// ---------------------------------------------------------------------------
__global__ void __launch_bounds__(256) agg_kernel(const float* __restrict__ A,
                                                  float* __restrict__ out) {
  __shared__ __align__(16) float s_red[8][DD];   // 8 KB

  const int row = blockIdx.x;
  const int tid = threadIdx.x;
  const int wid = tid >> 5;
  const int lane = tid & 31;

  const uint4* Aslice = (const uint4*)(A + (size_t)row * NN) + wid * 256;

  // Front-batch all 8 streaming loads (DRAM MLP = 8). Independent of he.
  uint4 av[8];
  #pragma unroll
  for (int r = 0; r < 8; r++)
    av[r] = __ldcs(Aslice + r * 32 + lane);

  // pending bit (r*4+c) = A[...] > 0 (a > 0 <=> bit pattern != 0).
  unsigned pending = 0u;
  #pragma unroll
  for (int r = 0; r < 8; r++) {
    unsigned f = 0u;
    if (av[r].x) f |= 1u;
    if (av[r].y) f |= 2u;
    if (av[r].z) f |= 4u;
    if (av[r].w) f |= 8u;
    pending |= f << (r * 4);
  }

#if __CUDA_ARCH__ >= 900
  cudaGridDependencySynchronize();   // he must be complete before gathering
#endif

  const uint4* he4 = (const uint4*)g_he;    // he row = 32 uint4 (256 halves)
  float acc[8] = {0.f, 0.f, 0.f, 0.f, 0.f, 0.f, 0.f, 0.f};

  while (true) {
    unsigned m = __ballot_sync(0xFFFFFFFFu, pending != 0u);
    if (!m) break;

    const int b = __ffs(pending) - 1;
    const int jmine = wid * 1024 + ((b & ~3) << 5) + (lane << 2) + (b & 3);

    const int n = __popc(m) < 4 ? __popc(m) : 4;
    int s0 = __ffs(m) - 1;            m &= m - 1;
    int s1 = m ? __ffs(m) - 1 : s0;   m &= m - 1;
    int s2 = m ? __ffs(m) - 1 : s0;   m &= m - 1;
    int s3 = m ? __ffs(m) - 1 : s0;

    const int j0 = __shfl_sync(0xFFFFFFFFu, jmine, s0);
    const int j1 = __shfl_sync(0xFFFFFFFFu, jmine, s1);
    const int j2 = __shfl_sync(0xFFFFFFFFu, jmine, s2);
    const int j3 = __shfl_sync(0xFFFFFFFFu, jmine, s3);

    if (lane == s0 || (n > 1 && lane == s1) || (n > 2 && lane == s2) ||
        (n > 3 && lane == s3))
      pending &= pending - 1u;

    uint4 v0, v1, v2, v3;
    v0 = __ldg(&he4[(size_t)j0 * 32 + lane]);
    if (n > 1) v1 = __ldg(&he4[(size_t)j1 * 32 + lane]);
    if (n > 2) v2 = __ldg(&he4[(size_t)j2 * 32 + lane]);
    if (n > 3) v3 = __ldg(&he4[(size_t)j3 * 32 + lane]);

    {
      const __half2* p = (const __half2*)&v0;
      #pragma unroll
      for (int q = 0; q < 4; q++) {
        const float2 f = __half22float2(p[q]);
        acc[2 * q] += f.x; acc[2 * q + 1] += f.y;
      }
    }
    if (n > 1) {
      const __half2* p = (const __half2*)&v1;
      #pragma unroll
      for (int q = 0; q < 4; q++) {
        const float2 f = __half22float2(p[q]);
        acc[2 * q] += f.x; acc[2 * q + 1] += f.y;
      }
    }
    if (n > 2) {
      const __half2* p = (const __half2*)&v2;
      #pragma unroll
      for (int q = 0; q < 4; q++) {
        const float2 f = __half22float2(p[q]);
        acc[2 * q] += f.x; acc[2 * q + 1] += f.y;
      }
    }
    if (n > 3) {
      const __half2* p = (const __half2*)&v3;
      #pragma unroll
      for (int q = 0; q < 4; q++) {
        const float2 f = __half22float2(p[q]);
        acc[2 * q] += f.x; acc[2 * q + 1] += f.y;
      }
    }
  }

  {
    float4* rr = (float4*)s_red[wid];
    rr[lane * 2]     = make_float4(acc[0], acc[1], acc[2], acc[3]);
    rr[lane * 2 + 1] = make_float4(acc[4], acc[5], acc[6], acc[7]);
  }
  __syncthreads();

  float s = 0.0f;
  #pragma unroll
  for (int w = 0; w < 8; w++) s += s_red[w][tid];
  out[(size_t)row * DD + tid] = s;
}

// ---------------------------------------------------------------------------
// Inputs (setup_inputs order):
//   0: graph_info [N*N], 1: h [N*D], 2: W1 [D*H], 3: b1 [H], 4: W2 [H], 5: b2 [1]
// Output: h_out [N*D] followed by e [N].
// mlp = PDL primary, agg = PDL secondary (overlapped A-scan).
// ---------------------------------------------------------------------------
extern "C" void kernel_launch(void* const* d_in, const int* in_sizes, int n_in,
                              void* d_out, int out_size) {
  const float* A  = (const float*)d_in[0];
  const float* h  = (const float*)d_in[1];
  const float* W1 = (const float*)d_in[2];
  const float* b1 = (const float*)d_in[3];
  const float* W2 = (const float*)d_in[4];
  const float* b2 = (const float*)d_in[5];

  float* out_h = (float*)d_out;                     // [N*D]
  float* out_e = (float*)d_out + (size_t)NN * DD;   // [N]

  mlp_kernel<<<NN / MLP_ROWS, 128>>>(h, W1, b1, W2, b2, out_e);

  // Secondary launch with programmatic stream serialization (PDL).
  {
    cudaLaunchConfig_t cfg = {};
    cfg.gridDim = dim3(NN, 1, 1);
    cfg.blockDim = dim3(256, 1, 1);
    cfg.dynamicSmemBytes = 0;
    cfg.stream = 0;
    cudaLaunchAttribute attrs[1];
    attrs[0].id = cudaLaunchAttributeProgrammaticStreamSerialization;
    attrs[0].val.programmaticStreamSerializationAllowed = 1;
    cfg.attrs = attrs;
    cfg.numAttrs = 1;
    cudaLaunchKernelEx(&cfg, agg_kernel, A, out_h);
  }
}